// round 8
// baseline (speedup 1.0000x reference)
#include <cuda_runtime.h>

#define FULLMASK 0xffffffffu
#define NEGC (-1000000000.0f)
#define FLR  (1e-30f)

__device__ __forceinline__ float lse2(float a, float b) {
    float mx = fmaxf(a, b);
    float mn = fminf(a, b);
    return mx + __logf(1.0f + __expf(mn - mx));
}
__device__ __forceinline__ float fmax3(float a, float b, float c) {
    return fmaxf(fmaxf(a, b), c);
}
__device__ __forceinline__ void relstore(int* p, int v) {
    asm volatile("st.release.cta.b32 [%0], %1;" :: "l"(p), "r"(v) : "memory");
}
__device__ __forceinline__ int acqload(int* p) {
    int v; asm volatile("ld.acquire.cta.b32 %0, [%1];" : "=r"(v) : "l"(p) : "memory");
    return v;
}

// One CTA (4 warps) per batch. Warp w owns columns 32w..32w+31 (1 col/lane).
// Fwd: left->right producer chain through per-row mailboxes (m,x,y at the
// boundary column). Bwd: right->left chain (u0, u2 at the boundary). Fused;
// logZ handed through shared memory under the release/acquire chain.
__global__ void __launch_bounds__(128, 1)
fb_kernel(const float* __restrict__ theta, const float* __restrict__ Aall,
          float* __restrict__ out)
{
    __shared__ float fm[3][128], fx[3][128], fy[3][128];   // fwd mailboxes
    __shared__ int   ff[3][128];
    __shared__ float bu0s[3][128], bu2s[3][128];           // bwd mailboxes
    __shared__ int   bf[3][128];
    __shared__ float shlogZ;

    const int tid  = threadIdx.x;
    const int w    = tid >> 5;
    const int lane = tid & 31;
    const int b    = blockIdx.x;

    for (int j = tid; j < 3 * 128; j += 128) {
        (&ff[0][0])[j] = 0;
        (&bf[0][0])[j] = 0;
    }
    __syncthreads();

    const float* Ab = Aall + (size_t)b * 9;
    const float A02 = Ab[2], A12 = Ab[5], A20 = Ab[6], A21 = Ab[7], A22 = Ab[8];
    float E[9];
#pragma unroll
    for (int t = 0; t < 9; t++) E[t] = __expf(Ab[t]);
    const float eM0 = E[0], eM1 = E[3], eM2 = E[6];   // exp(A[:,0])
    const float eX0 = E[1], eX1 = E[4], eX2 = E[7];   // exp(A[:,1])

    const size_t base = (size_t)b * 49152;
    const float* th = theta + base;
    float* po = out + base;

    float lzreg = 0.0f;

    // ====================== FORWARD ======================
    {
        const int col = w * 32 + lane;
        const int off = col * 3;           // float offset within a 384-float row
        float pm = NEGC, px = NEGC, py = NEGC;
        float la0 = NEGC, la1 = NEGC, la2 = NEGC;

        float t0 = th[off], t1 = th[off + 1], t2 = th[off + 2];
        for (int i = 0; i < 128; i++) {
            float n0, n1, n2;
            if (i < 127) {
                int r = (i + 1) * 384 + off;
                n0 = th[r]; n1 = th[r + 1]; n2 = th[r + 2];
            }

            float hm = NEGC, hx = NEGC, hy = NEGC;
            float dM = NEGC, dX = NEGC, dY = NEGC;
            if (w > 0) {
                while (acqload(&ff[w - 1][i]) == 0) { __nanosleep(32); }
                hm = fm[w - 1][i]; hx = fx[w - 1][i]; hy = fy[w - 1][i];
                if (i > 0) { dM = fm[w - 1][i - 1]; dX = fx[w - 1][i - 1]; dY = fy[w - 1][i - 1]; }
            }

            // shared-exp rep of own prev-row triple
            float r0 = fmax3(pm, px, py);
            float Em = __expf(pm - r0), Ex = __expf(px - r0), Ey = __expf(py - r0);
            // col-1 prev-row rep
            float rs  = __shfl_up_sync(FULLMASK, r0, 1);
            float Ems = __shfl_up_sync(FULLMASK, Em, 1);
            float Exs = __shfl_up_sync(FULLMASK, Ex, 1);
            float Eys = __shfl_up_sync(FULLMASK, Ey, 1);
            if (lane == 0) {
                if (w == 0) { rs = NEGC; Ems = 0.f; Exs = 0.f; Eys = 0.f; }
                else {
                    rs = fmax3(dM, dX, dY);
                    Ems = __expf(dM - rs); Exs = __expf(dX - rs); Eys = __expf(dY - rs);
                }
            }

            float lm = rs + __logf(fmaf(eM0, Ems, fmaf(eM1, Exs, fmaf(eM2, Eys, FLR))));
            if (w == 0 && i == 0 && lane == 0) lm = 0.0f;   // start cell (0,0,match)
            float m = t0 + lm;
            float x = t1 + r0 + __logf(fmaf(eX0, Em, fmaf(eX1, Ex, fmaf(eX2, Ey, FLR))));

            float mnb = __shfl_up_sync(FULLMASK, m, 1);
            float xnb = __shfl_up_sync(FULLMASK, x, 1);
            if (lane == 0) { mnb = (w == 0) ? NEGC : hm; xnb = (w == 0) ? NEGC : hx; }

            float c = t2 + lse2(mnb + A02, xnb + A12);
            float d = t2 + A22;

            float C = c, D = d;
#pragma unroll
            for (int off2 = 1; off2 < 32; off2 <<= 1) {
                float Cu = __shfl_up_sync(FULLMASK, C, off2);
                float Du = __shfl_up_sync(FULLMASK, D, off2);
                if (lane >= off2) { C = lse2(C, D + Cu); D += Du; }
            }
            float Ce = __shfl_up_sync(FULLMASK, C, 1);
            float De = __shfl_up_sync(FULLMASK, D, 1);
            float seed = (w == 0) ? NEGC : hy;
            float yin = (lane == 0) ? seed : lse2(Ce, De + seed);
            float y = lse2(c, d + yin);

            int wo = i * 384 + off;
            po[wo] = m; po[wo + 1] = x; po[wo + 2] = y;

            if (w < 3 && lane == 31) {
                fm[w][i] = m; fx[w][i] = x; fy[w][i] = y;
                relstore(&ff[w][i], 1);
            }
            if (i == 127) { la0 = m; la1 = x; la2 = y; }

            pm = m; px = x; py = y;
            if (i < 127) { t0 = n0; t1 = n1; t2 = n2; }
        }
        if (w == 3) {   // logZ from alpha(127,127,:) in lane 31
            la0 = __shfl_sync(FULLMASK, la0, 31);
            la1 = __shfl_sync(FULLMASK, la1, 31);
            la2 = __shfl_sync(FULLMASK, la2, 31);
            float r = fmax3(la0, la1, la2);
            lzreg = r + __logf(__expf(la0 - r) + __expf(la1 - r) + __expf(la2 - r));
            if (lane == 31) shlogZ = lzreg;   // published by first bwd release
        }
    }

    // ====================== BACKWARD + COMBINE ======================
    {
        const int v = 3 - w;                 // v=0 is the rightmost (producer) warp
        const int col = 32 * w + 31 - lane;  // scan pos p = 32v+lane -> col = 127-p
        const int off = col * 3;
        float u0p = NEGC, u1p = NEGC;
        float lz = lzreg;                    // valid for v==0 (w==3)

        float t0 = th[127 * 384 + off], t1 = th[127 * 384 + off + 1], t2 = th[127 * 384 + off + 2];
        for (int i = 127; i >= 0; i--) {
            const int ro = i * 384 + off;
            float a0 = po[ro], a1 = po[ro + 1], a2 = po[ro + 2];
            float n0, n1, n2;
            if (i > 0) {
                int r = (i - 1) * 384 + off;
                n0 = th[r]; n1 = th[r + 1]; n2 = th[r + 2];
            }

            float seed = NEGC, u0ext = NEGC;
            if (v > 0) {
                while (acqload(&bf[v - 1][i]) == 0) { __nanosleep(32); }
                if (i == 127) lz = shlogZ;
                seed  = bu2s[v - 1][i];
                u0ext = (i < 127) ? bu0s[v - 1][i + 1] : NEGC;
            }

            float u0n = __shfl_up_sync(FULLMASK, u0p, 1);
            if (lane == 0) u0n = (v == 0) ? NEGC : u0ext;

            const bool lastcell = (v == 0 && lane == 0 && i == 127);
            float c = t2 + lse2(A20 + u0n, A21 + u1p);
            float d = t2 + A22;
            if (lastcell) { c = t2; d = NEGC; }   // beta(127,127)=0

            float C = c, D = d;
#pragma unroll
            for (int off2 = 1; off2 < 32; off2 <<= 1) {
                float Cu = __shfl_up_sync(FULLMASK, C, off2);
                float Du = __shfl_up_sync(FULLMASK, D, off2);
                if (lane >= off2) { C = lse2(C, D + Cu); D += Du; }
            }
            float Ce = __shfl_up_sync(FULLMASK, C, 1);
            float De = __shfl_up_sync(FULLMASK, D, 1);
            float yin = (lane == 0) ? seed : lse2(Ce, De + seed);

            float wr = yin;   // u2 at col j+1 (exclusive), current row
            float rr = fmax3(u0n, u1p, wr);
            float e0 = __expf(u0n - rr), e1 = __expf(u1p - rr), e2 = __expf(wr - rr);
            float bb0 = rr + __logf(fmaf(E[0], e0, fmaf(E[1], e1, fmaf(E[2], e2, FLR))));
            float bb1 = rr + __logf(fmaf(E[3], e0, fmaf(E[4], e1, fmaf(E[5], e2, FLR))));
            float bb2 = rr + __logf(fmaf(E[6], e0, fmaf(E[7], e1, fmaf(E[8], e2, FLR))));
            if (lastcell) { bb0 = 0.f; bb1 = 0.f; bb2 = 0.f; }

            po[ro]     = (a0 + bb0) - lz;
            po[ro + 1] = (a1 + bb1) - lz;
            po[ro + 2] = (a2 + bb2) - lz;

            float nu0 = bb0 + t0;
            float nu1 = bb1 + t1;

            if (v < 3 && lane == 31) {
                bu0s[v][i] = nu0;
                bu2s[v][i] = lse2(c, d + yin);   // inclusive u2 at this column
                relstore(&bf[v][i], 1);
            }
            u0p = nu0; u1p = nu1;
            if (i > 0) { t0 = n0; t1 = n1; t2 = n2; }
        }
    }
}

extern "C" void kernel_launch(void* const* d_in, const int* in_sizes, int n_in,
                              void* d_out, int out_size)
{
    const float* theta = (const float*)d_in[0];
    const float* A     = (const float*)d_in[1];
    float* out         = (float*)d_out;
    int B = in_sizes[1] / 9;   // 256
    fb_kernel<<<B, 128>>>(theta, A, out);
}

// round 9
// speedup vs baseline: 1.5595x; 1.5595x over previous
#include <cuda_runtime.h>

#define FULLMASK 0xffffffffu
#define NEGC (-1000000000.0f)
#define FLR  (1e-30f)

__device__ __forceinline__ float lse2(float a, float b) {
    float mx = fmaxf(a, b);
    float mn = fminf(a, b);
    return mx + __logf(1.0f + __expf(mn - mx));
}
__device__ __forceinline__ float fmax3(float a, float b, float c) {
    return fmaxf(fmaxf(a, b), c);
}
__device__ __forceinline__ void relstore(int* p, int v) {
    asm volatile("st.release.cta.b32 [%0], %1;" :: "l"(p), "r"(v) : "memory");
}
__device__ __forceinline__ int acqload(int* p) {
    int v; asm volatile("ld.acquire.cta.b32 %0, [%1];" : "=r"(v) : "l"(p) : "memory");
    return v;
}

// One CTA (4 warps) per batch. Warp w owns columns 32w..32w+31 (1 col/lane).
// Fwd: left->right producer chain through per-row mailboxes (m,x,y at the
// boundary column). Bwd: right->left chain (u0, u2 at the boundary). Fused;
// logZ handed through shared memory under the release/acquire chain.
__global__ void __launch_bounds__(128, 1)
fb_kernel(const float* __restrict__ theta, const float* __restrict__ Aall,
          float* __restrict__ out)
{
    __shared__ float fm[3][128], fx[3][128], fy[3][128];   // fwd mailboxes
    __shared__ int   ff[3][128];
    __shared__ float bu0s[3][128], bu2s[3][128];           // bwd mailboxes
    __shared__ int   bf[3][128];
    __shared__ float shlogZ;

    const int tid  = threadIdx.x;
    const int w    = tid >> 5;
    const int lane = tid & 31;
    const int b    = blockIdx.x;

    for (int j = tid; j < 3 * 128; j += 128) {
        (&ff[0][0])[j] = 0;
        (&bf[0][0])[j] = 0;
    }
    __syncthreads();

    const float* Ab = Aall + (size_t)b * 9;
    const float A02 = Ab[2], A12 = Ab[5], A20 = Ab[6], A21 = Ab[7], A22 = Ab[8];
    float E[9];
#pragma unroll
    for (int t = 0; t < 9; t++) E[t] = __expf(Ab[t]);
    const float eM0 = E[0], eM1 = E[3], eM2 = E[6];   // exp(A[:,0])
    const float eX0 = E[1], eX1 = E[4], eX2 = E[7];   // exp(A[:,1])

    const size_t base = (size_t)b * 49152;
    const float* th = theta + base;
    float* po = out + base;

    float lzreg = 0.0f;

    // ====================== FORWARD ======================
    {
        const int col = w * 32 + lane;
        const int off = col * 3;           // float offset within a 384-float row
        float pm = NEGC, px = NEGC, py = NEGC;
        float la0 = NEGC, la1 = NEGC, la2 = NEGC;

        float t0 = th[off], t1 = th[off + 1], t2 = th[off + 2];
        for (int i = 0; i < 128; i++) {
            float n0, n1, n2;
            if (i < 127) {
                int r = (i + 1) * 384 + off;
                n0 = th[r]; n1 = th[r + 1]; n2 = th[r + 2];
            }

            float hm = NEGC, hx = NEGC, hy = NEGC;
            float dM = NEGC, dX = NEGC, dY = NEGC;
            if (w > 0) {
                while (acqload(&ff[w - 1][i]) == 0) { __nanosleep(32); }
                hm = fm[w - 1][i]; hx = fx[w - 1][i]; hy = fy[w - 1][i];
                if (i > 0) { dM = fm[w - 1][i - 1]; dX = fx[w - 1][i - 1]; dY = fy[w - 1][i - 1]; }
            }

            // shared-exp rep of own prev-row triple
            float r0 = fmax3(pm, px, py);
            float Em = __expf(pm - r0), Ex = __expf(px - r0), Ey = __expf(py - r0);
            // col-1 prev-row rep
            float rs  = __shfl_up_sync(FULLMASK, r0, 1);
            float Ems = __shfl_up_sync(FULLMASK, Em, 1);
            float Exs = __shfl_up_sync(FULLMASK, Ex, 1);
            float Eys = __shfl_up_sync(FULLMASK, Ey, 1);
            if (lane == 0) {
                if (w == 0) { rs = NEGC; Ems = 0.f; Exs = 0.f; Eys = 0.f; }
                else {
                    rs = fmax3(dM, dX, dY);
                    Ems = __expf(dM - rs); Exs = __expf(dX - rs); Eys = __expf(dY - rs);
                }
            }

            float lm = rs + __logf(fmaf(eM0, Ems, fmaf(eM1, Exs, fmaf(eM2, Eys, FLR))));
            if (w == 0 && i == 0 && lane == 0) lm = 0.0f;   // start cell (0,0,match)
            float m = t0 + lm;
            float x = t1 + r0 + __logf(fmaf(eX0, Em, fmaf(eX1, Ex, fmaf(eX2, Ey, FLR))));

            float mnb = __shfl_up_sync(FULLMASK, m, 1);
            float xnb = __shfl_up_sync(FULLMASK, x, 1);
            if (lane == 0) { mnb = (w == 0) ? NEGC : hm; xnb = (w == 0) ? NEGC : hx; }

            float c = t2 + lse2(mnb + A02, xnb + A12);
            float d = t2 + A22;

            float C = c, D = d;
#pragma unroll
            for (int off2 = 1; off2 < 32; off2 <<= 1) {
                float Cu = __shfl_up_sync(FULLMASK, C, off2);
                float Du = __shfl_up_sync(FULLMASK, D, off2);
                if (lane >= off2) { C = lse2(C, D + Cu); D += Du; }
            }
            float Ce = __shfl_up_sync(FULLMASK, C, 1);
            float De = __shfl_up_sync(FULLMASK, D, 1);
            float seed = (w == 0) ? NEGC : hy;
            float yin = (lane == 0) ? seed : lse2(Ce, De + seed);
            float y = lse2(c, d + yin);

            int wo = i * 384 + off;
            po[wo] = m; po[wo + 1] = x; po[wo + 2] = y;

            if (w < 3 && lane == 31) {
                fm[w][i] = m; fx[w][i] = x; fy[w][i] = y;
                relstore(&ff[w][i], 1);
            }
            if (i == 127) { la0 = m; la1 = x; la2 = y; }

            pm = m; px = x; py = y;
            if (i < 127) { t0 = n0; t1 = n1; t2 = n2; }
        }
        if (w == 3) {   // logZ from alpha(127,127,:) in lane 31
            la0 = __shfl_sync(FULLMASK, la0, 31);
            la1 = __shfl_sync(FULLMASK, la1, 31);
            la2 = __shfl_sync(FULLMASK, la2, 31);
            float r = fmax3(la0, la1, la2);
            lzreg = r + __logf(__expf(la0 - r) + __expf(la1 - r) + __expf(la2 - r));
            if (lane == 31) shlogZ = lzreg;   // published by first bwd release
        }
    }

    // ====================== BACKWARD + COMBINE ======================
    {
        const int v = 3 - w;                 // v=0 is the rightmost (producer) warp
        const int col = 32 * w + 31 - lane;  // scan pos p = 32v+lane -> col = 127-p
        const int off = col * 3;
        float u0p = NEGC, u1p = NEGC;
        float lz = lzreg;                    // valid for v==0 (w==3)

        float t0 = th[127 * 384 + off], t1 = th[127 * 384 + off + 1], t2 = th[127 * 384 + off + 2];
        for (int i = 127; i >= 0; i--) {
            const int ro = i * 384 + off;
            float a0 = po[ro], a1 = po[ro + 1], a2 = po[ro + 2];
            float n0, n1, n2;
            if (i > 0) {
                int r = (i - 1) * 384 + off;
                n0 = th[r]; n1 = th[r + 1]; n2 = th[r + 2];
            }

            float seed = NEGC, u0ext = NEGC;
            if (v > 0) {
                while (acqload(&bf[v - 1][i]) == 0) { __nanosleep(32); }
                if (i == 127) lz = shlogZ;
                seed  = bu2s[v - 1][i];
                u0ext = (i < 127) ? bu0s[v - 1][i + 1] : NEGC;
            }

            float u0n = __shfl_up_sync(FULLMASK, u0p, 1);
            if (lane == 0) u0n = (v == 0) ? NEGC : u0ext;

            const bool lastcell = (v == 0 && lane == 0 && i == 127);
            float c = t2 + lse2(A20 + u0n, A21 + u1p);
            float d = t2 + A22;
            if (lastcell) { c = t2; d = NEGC; }   // beta(127,127)=0

            float C = c, D = d;
#pragma unroll
            for (int off2 = 1; off2 < 32; off2 <<= 1) {
                float Cu = __shfl_up_sync(FULLMASK, C, off2);
                float Du = __shfl_up_sync(FULLMASK, D, off2);
                if (lane >= off2) { C = lse2(C, D + Cu); D += Du; }
            }
            float Ce = __shfl_up_sync(FULLMASK, C, 1);
            float De = __shfl_up_sync(FULLMASK, D, 1);
            float yin = (lane == 0) ? seed : lse2(Ce, De + seed);

            float wr = yin;   // u2 at col j+1 (exclusive), current row
            float rr = fmax3(u0n, u1p, wr);
            float e0 = __expf(u0n - rr), e1 = __expf(u1p - rr), e2 = __expf(wr - rr);
            float bb0 = rr + __logf(fmaf(E[0], e0, fmaf(E[1], e1, fmaf(E[2], e2, FLR))));
            float bb1 = rr + __logf(fmaf(E[3], e0, fmaf(E[4], e1, fmaf(E[5], e2, FLR))));
            float bb2 = rr + __logf(fmaf(E[6], e0, fmaf(E[7], e1, fmaf(E[8], e2, FLR))));
            if (lastcell) { bb0 = 0.f; bb1 = 0.f; bb2 = 0.f; }

            po[ro]     = (a0 + bb0) - lz;
            po[ro + 1] = (a1 + bb1) - lz;
            po[ro + 2] = (a2 + bb2) - lz;

            float nu0 = bb0 + t0;
            float nu1 = bb1 + t1;

            if (v < 3 && lane == 31) {
                bu0s[v][i] = nu0;
                bu2s[v][i] = lse2(c, d + yin);   // inclusive u2 at this column
                relstore(&bf[v][i], 1);
            }
            u0p = nu0; u1p = nu1;
            if (i > 0) { t0 = n0; t1 = n1; t2 = n2; }
        }
    }
}

extern "C" void kernel_launch(void* const* d_in, const int* in_sizes, int n_in,
                              void* d_out, int out_size)
{
    const float* theta = (const float*)d_in[0];
    const float* A     = (const float*)d_in[1];
    float* out         = (float*)d_out;
    int B = in_sizes[1] / 9;   // 256
    fb_kernel<<<B, 128>>>(theta, A, out);
}

// round 10
// speedup vs baseline: 2.2462x; 1.4403x over previous
#include <cuda_runtime.h>

#define FULLMASK 0xffffffffu
#define NEGC (-1000000000.0f)
#define FLR  (1e-30f)

__device__ float g_beta[256 * 128 * 128 * 3];   // beta scratch (50.3 MB)

__device__ __forceinline__ float lse2(float a, float b) {
    float mx = fmaxf(a, b);
    float mn = fminf(a, b);
    return mx + __logf(1.0f + __expf(mn - mx));
}
__device__ __forceinline__ float fmax3(float a, float b, float c) {
    return fmaxf(fmaxf(a, b), c);
}
__device__ __forceinline__ void relstore(int* p, int v) {
    asm volatile("st.release.cta.b32 [%0], %1;" :: "l"(p), "r"(v) : "memory");
}
__device__ __forceinline__ int acqload(int* p) {
    int v; asm volatile("ld.acquire.cta.b32 %0, [%1];" : "=r"(v) : "l"(p) : "memory");
    return v;
}

// One CTA (8 warps) per batch. Warps 0-3: forward alpha (cols 32w..32w+31,
// 1 col/lane, left->right mailbox chain), written to `out`. Warps 4-7: beta
// lattice (independent of alpha!), right->left mailbox chain, written to
// g_beta. Then one __syncthreads and a coalesced float4 combine:
// out = alpha + beta - logZ.
__global__ void __launch_bounds__(256, 1)
fb_kernel(const float* __restrict__ theta, const float* __restrict__ Aall,
          float* __restrict__ out)
{
    __shared__ float fm[3][128], fx[3][128], fy[3][128];   // fwd mailboxes
    __shared__ int   ff[3][128];
    __shared__ float bu0s[3][128], bu2s[3][128];           // beta mailboxes
    __shared__ int   bf[3][128];
    __shared__ float shlogZ;

    const int tid  = threadIdx.x;
    const int w    = tid >> 5;
    const int lane = tid & 31;
    const int b    = blockIdx.x;

    for (int j = tid; j < 3 * 128; j += 256) {
        (&ff[0][0])[j] = 0;
        (&bf[0][0])[j] = 0;
    }
    __syncthreads();

    const float* Ab = Aall + (size_t)b * 9;
    const float A02 = Ab[2], A12 = Ab[5], A20 = Ab[6], A21 = Ab[7], A22 = Ab[8];
    float E[9];
#pragma unroll
    for (int t = 0; t < 9; t++) E[t] = __expf(Ab[t]);
    const float eM0 = E[0], eM1 = E[3], eM2 = E[6];   // exp(A[:,0])
    const float eX0 = E[1], eX1 = E[4], eX2 = E[7];   // exp(A[:,1])

    const size_t base = (size_t)b * 49152;
    const float* th = theta + base;
    float* po = out + base;
    float* pb = g_beta + base;

    if (w < 4) {
        // ====================== FORWARD (alpha) ======================
        const int col = w * 32 + lane;
        const int off = col * 3;           // float offset within a 384-float row
        float pm = NEGC, px = NEGC, py = NEGC;
        float la0 = NEGC, la1 = NEGC, la2 = NEGC;

        float t0 = th[off], t1 = th[off + 1], t2 = th[off + 2];
        for (int i = 0; i < 128; i++) {
            float n0, n1, n2;
            if (i < 127) {
                int r = (i + 1) * 384 + off;
                n0 = th[r]; n1 = th[r + 1]; n2 = th[r + 2];
            }

            float hm = NEGC, hx = NEGC, hy = NEGC;
            float dM = NEGC, dX = NEGC, dY = NEGC;
            if (w > 0) {
                if (acqload(&ff[w - 1][i]) == 0) {
                    while (acqload(&ff[w - 1][i]) == 0) { __nanosleep(32); }
                }
                hm = fm[w - 1][i]; hx = fx[w - 1][i]; hy = fy[w - 1][i];
                if (i > 0) { dM = fm[w - 1][i - 1]; dX = fx[w - 1][i - 1]; dY = fy[w - 1][i - 1]; }
            }

            // shared-exp rep of own prev-row triple
            float r0 = fmax3(pm, px, py);
            float Em = __expf(pm - r0), Ex = __expf(px - r0), Ey = __expf(py - r0);
            // col-1 prev-row rep
            float rs  = __shfl_up_sync(FULLMASK, r0, 1);
            float Ems = __shfl_up_sync(FULLMASK, Em, 1);
            float Exs = __shfl_up_sync(FULLMASK, Ex, 1);
            float Eys = __shfl_up_sync(FULLMASK, Ey, 1);
            if (lane == 0) {
                if (w == 0) { rs = NEGC; Ems = 0.f; Exs = 0.f; Eys = 0.f; }
                else {
                    rs = fmax3(dM, dX, dY);
                    Ems = __expf(dM - rs); Exs = __expf(dX - rs); Eys = __expf(dY - rs);
                }
            }

            float lm = rs + __logf(fmaf(eM0, Ems, fmaf(eM1, Exs, fmaf(eM2, Eys, FLR))));
            if (w == 0 && i == 0 && lane == 0) lm = 0.0f;   // start cell (0,0,match)
            float m = t0 + lm;
            float x = t1 + r0 + __logf(fmaf(eX0, Em, fmaf(eX1, Ex, fmaf(eX2, Ey, FLR))));

            float mnb = __shfl_up_sync(FULLMASK, m, 1);
            float xnb = __shfl_up_sync(FULLMASK, x, 1);
            if (lane == 0) { mnb = (w == 0) ? NEGC : hm; xnb = (w == 0) ? NEGC : hx; }

            float c = t2 + lse2(mnb + A02, xnb + A12);
            float d = t2 + A22;

            float C = c, D = d;
#pragma unroll
            for (int off2 = 1; off2 < 32; off2 <<= 1) {
                float Cu = __shfl_up_sync(FULLMASK, C, off2);
                float Du = __shfl_up_sync(FULLMASK, D, off2);
                if (lane >= off2) { C = lse2(C, D + Cu); D += Du; }
            }
            float Ce = __shfl_up_sync(FULLMASK, C, 1);
            float De = __shfl_up_sync(FULLMASK, D, 1);
            float seed = (w == 0) ? NEGC : hy;
            float yin = (lane == 0) ? seed : lse2(Ce, De + seed);
            float y = lse2(c, d + yin);

            int wo = i * 384 + off;
            po[wo] = m; po[wo + 1] = x; po[wo + 2] = y;

            if (w < 3 && lane == 31) {
                fm[w][i] = m; fx[w][i] = x; fy[w][i] = y;
                relstore(&ff[w][i], 1);
            }
            if (i == 127) { la0 = m; la1 = x; la2 = y; }

            pm = m; px = x; py = y;
            if (i < 127) { t0 = n0; t1 = n1; t2 = n2; }
        }
        if (w == 3) {   // logZ from alpha(127,127,:) in lane 31
            la0 = __shfl_sync(FULLMASK, la0, 31);
            la1 = __shfl_sync(FULLMASK, la1, 31);
            la2 = __shfl_sync(FULLMASK, la2, 31);
            float r = fmax3(la0, la1, la2);
            float lz = r + __logf(__expf(la0 - r) + __expf(la1 - r) + __expf(la2 - r));
            if (lane == 31) shlogZ = lz;
        }
    } else {
        // ====================== BETA (independent lattice) ======================
        const int wl = w - 4;                 // 0..3
        const int v = 3 - wl;                 // v=0 is the rightmost (producer) warp
        const int col = 32 * wl + 31 - lane;  // scan pos p = 32v+lane -> col = 127-p
        const int off = col * 3;
        float u0p = NEGC, u1p = NEGC;

        float t0 = th[127 * 384 + off], t1 = th[127 * 384 + off + 1], t2 = th[127 * 384 + off + 2];
        for (int i = 127; i >= 0; i--) {
            float n0, n1, n2;
            if (i > 0) {
                int r = (i - 1) * 384 + off;
                n0 = th[r]; n1 = th[r + 1]; n2 = th[r + 2];
            }

            float seed = NEGC, u0ext = NEGC;
            if (v > 0) {
                if (acqload(&bf[v - 1][i]) == 0) {
                    while (acqload(&bf[v - 1][i]) == 0) { __nanosleep(32); }
                }
                seed  = bu2s[v - 1][i];
                u0ext = (i < 127) ? bu0s[v - 1][i + 1] : NEGC;
            }

            float u0n = __shfl_up_sync(FULLMASK, u0p, 1);
            if (lane == 0) u0n = (v == 0) ? NEGC : u0ext;

            const bool lastcell = (v == 0 && lane == 0 && i == 127);
            float c = t2 + lse2(A20 + u0n, A21 + u1p);
            float d = t2 + A22;
            if (lastcell) { c = t2; d = NEGC; }   // beta(127,127)=0

            float C = c, D = d;
#pragma unroll
            for (int off2 = 1; off2 < 32; off2 <<= 1) {
                float Cu = __shfl_up_sync(FULLMASK, C, off2);
                float Du = __shfl_up_sync(FULLMASK, D, off2);
                if (lane >= off2) { C = lse2(C, D + Cu); D += Du; }
            }
            float Ce = __shfl_up_sync(FULLMASK, C, 1);
            float De = __shfl_up_sync(FULLMASK, D, 1);
            float yin = (lane == 0) ? seed : lse2(Ce, De + seed);

            float wr = yin;   // u2 at col j+1 (exclusive), current row
            float rr = fmax3(u0n, u1p, wr);
            float e0 = __expf(u0n - rr), e1 = __expf(u1p - rr), e2 = __expf(wr - rr);
            float bb0 = rr + __logf(fmaf(E[0], e0, fmaf(E[1], e1, fmaf(E[2], e2, FLR))));
            float bb1 = rr + __logf(fmaf(E[3], e0, fmaf(E[4], e1, fmaf(E[5], e2, FLR))));
            float bb2 = rr + __logf(fmaf(E[6], e0, fmaf(E[7], e1, fmaf(E[8], e2, FLR))));
            if (lastcell) { bb0 = 0.f; bb1 = 0.f; bb2 = 0.f; }

            int ro = i * 384 + off;
            pb[ro] = bb0; pb[ro + 1] = bb1; pb[ro + 2] = bb2;

            float nu0 = bb0 + t0;
            float nu1 = bb1 + t1;

            if (v < 3 && lane == 31) {
                bu0s[v][i] = nu0;
                bu2s[v][i] = lse2(c, d + yin);   // inclusive u2 at this column
                relstore(&bf[v][i], 1);
            }
            u0p = nu0; u1p = nu1;
            if (i > 0) { t0 = n0; t1 = n1; t2 = n2; }
        }
    }

    // ====================== COMBINE ======================
    __syncthreads();
    const float lz = shlogZ;
    const float4* bp4 = reinterpret_cast<const float4*>(pb);
    float4* op4 = reinterpret_cast<float4*>(po);
#pragma unroll 4
    for (int t = tid; t < 12288; t += 256) {
        float4 a = op4[t];
        float4 bb = bp4[t];
        op4[t] = make_float4(a.x + bb.x - lz, a.y + bb.y - lz,
                             a.z + bb.z - lz, a.w + bb.w - lz);
    }
}

extern "C" void kernel_launch(void* const* d_in, const int* in_sizes, int n_in,
                              void* d_out, int out_size)
{
    const float* theta = (const float*)d_in[0];
    const float* A     = (const float*)d_in[1];
    float* out         = (float*)d_out;
    int B = in_sizes[1] / 9;   // 256
    fb_kernel<<<B, 256>>>(theta, A, out);
}